// round 2
// baseline (speedup 1.0000x reference)
#include <cuda_runtime.h>
#include <cstdint>
#include <cfloat>

#define NROW 32768
#define NCOL 1024
#define DIM 64
#define ITERS 100
#define SINK_BLOCKS 128
#define XQ_ELEMS (NROW * DIM)          // 2097152
#define LOSS_OFF XQ_ELEMS
#define IDX_OFF (XQ_ELEMS + 1)

// ---------------- device scratch (static: no runtime allocation) ----------------
__device__ float    g_P[(size_t)NROW * NCOL];     // d, then P' = exp(a*(middle-d)); 134MB
__device__ float    g_xx[NROW];
__device__ float    g_ww[NCOL];
__device__ float    g_colsum[ITERS][NCOL];        // per-iteration column sums
__device__ float    g_R[NROW];                    // final-iteration row factors
__device__ int      g_idxQ[NROW];
__device__ int      g_idxD[NROW];
__device__ int      g_bad;
__device__ float    g_losspart[4096];
__device__ unsigned g_dmin_u, g_dmax_u;
__device__ float    g_middle, g_sc;
__device__ unsigned g_barrier;

// monotone float<->unsigned map for atomicMin/Max ordering
__device__ __forceinline__ unsigned fmapu(float f) {
    unsigned u = __float_as_uint(f);
    return (u & 0x80000000u) ? ~u : (u | 0x80000000u);
}
__device__ __forceinline__ float funmap(unsigned m) {
    unsigned v = (m & 0x80000000u) ? (m & 0x7fffffffu) : ~m;
    return __uint_as_float(v);
}

// FFMA-only exp (no MUFU). Valid for |x| <= ~25. Max rel err ~1.2e-7.
__device__ __forceinline__ float fexp(float x) {
    float t = x * 1.4426950408889634f;   // x * log2(e)
    float r = rintf(t);
    float g = (t - r) * 0.6931471805599453f;   // in [-0.3466, 0.3466]
    float p = 1.0f + g * (1.0f + g * (0.5f + g * (0.16666666667f +
              g * (0.041666666667f + g * (0.0083333333333f + g * 0.0013888888889f)))));
    int ir = (int)r;
    float s = __int_as_float((ir + 127) << 23);
    return p * s;
}

// ---------------- init: zero per-iteration colsums + scalars ----------------
__global__ void k_init() {
    int i = blockIdx.x * blockDim.x + threadIdx.x;
    if (i < ITERS * NCOL) ((float*)g_colsum)[i] = 0.0f;
    if (i == 0) {
        g_barrier = 0u;
        g_bad = 0;
        g_dmin_u = 0xFFFFFFFFu;
        g_dmax_u = 0u;
    }
}

// ---------------- squared norms: one warp per row ----------------
__global__ void k_norms(const float* __restrict__ x, const float* __restrict__ W) {
    int gw = blockIdx.x * 8 + (threadIdx.x >> 5);
    int lane = threadIdx.x & 31;
    if (gw >= NROW + NCOL) return;
    const float* src = (gw < NROW) ? (x + (size_t)gw * DIM)
                                   : (W + (size_t)(gw - NROW) * DIM);
    float2 v = ((const float2*)src)[lane];
    float s = v.x * v.x + v.y * v.y;
#pragma unroll
    for (int o = 16; o; o >>= 1) s += __shfl_xor_sync(0xffffffffu, s, o);
    if (lane == 0) {
        if (gw < NROW) g_xx[gw] = s;
        else           g_ww[gw - NROW] = s;
    }
}

// ---------------- d = xx + ww - 2 x@W^T (fp32 FFMA, 64x64 tiles); global min/max of d ----------------
__global__ void __launch_bounds__(256) k_gemm(const float* __restrict__ x,
                                              const float* __restrict__ W) {
    __shared__ float xsT[64][68];   // [d][r], transposed; 272B row pitch (16B-aligned)
    __shared__ float wsT[64][68];
    int tid = threadIdx.x;
    int r0 = blockIdx.x * 64;
    int c0 = blockIdx.y * 64;

    for (int n = tid; n < 1024; n += 256) {
        int r = n >> 4, d4 = (n & 15) << 2;
        float4 v = *(const float4*)(x + (size_t)(r0 + r) * DIM + d4);
        xsT[d4 + 0][r] = v.x; xsT[d4 + 1][r] = v.y;
        xsT[d4 + 2][r] = v.z; xsT[d4 + 3][r] = v.w;
        float4 u = *(const float4*)(W + (size_t)(c0 + r) * DIM + d4);
        wsT[d4 + 0][r] = u.x; wsT[d4 + 1][r] = u.y;
        wsT[d4 + 2][r] = u.z; wsT[d4 + 3][r] = u.w;
    }
    __syncthreads();

    int tx = tid & 15, ty = tid >> 4;
    float acc[4][4];
#pragma unroll
    for (int i = 0; i < 4; ++i)
#pragma unroll
        for (int j = 0; j < 4; ++j) acc[i][j] = 0.0f;

#pragma unroll 8
    for (int d = 0; d < 64; ++d) {
        float4 a = *(const float4*)&xsT[d][ty * 4];
        float4 b = *(const float4*)&wsT[d][tx * 4];
        float av[4] = {a.x, a.y, a.z, a.w};
        float bv[4] = {b.x, b.y, b.z, b.w};
#pragma unroll
        for (int i = 0; i < 4; ++i)
#pragma unroll
            for (int j = 0; j < 4; ++j) acc[i][j] += av[i] * bv[j];
    }

    float mn = FLT_MAX, mx = -FLT_MAX;
#pragma unroll
    for (int i = 0; i < 4; ++i) {
        int row = r0 + ty * 4 + i;
        float xxv = g_xx[row];
        float dv[4];
#pragma unroll
        for (int j = 0; j < 4; ++j) {
            dv[j] = (xxv + g_ww[c0 + tx * 4 + j]) - 2.0f * acc[i][j];
            mn = fminf(mn, dv[j]);
            mx = fmaxf(mx, dv[j]);
        }
        *(float4*)(g_P + (size_t)row * NCOL + c0 + tx * 4) =
            make_float4(dv[0], dv[1], dv[2], dv[3]);
    }

    __shared__ float smn[256], smx[256];
    smn[tid] = mn; smx[tid] = mx;
    __syncthreads();
    for (int s = 128; s; s >>= 1) {
        if (tid < s) {
            smn[tid] = fminf(smn[tid], smn[tid + s]);
            smx[tid] = fmaxf(smx[tid], smx[tid + s]);
        }
        __syncthreads();
    }
    if (tid == 0) {
        atomicMin(&g_dmin_u, fmapu(smn[0]));
        atomicMax(&g_dmax_u, fmapu(smx[0]));
    }
}

// ---------------- scalar constants ----------------
__global__ void k_consts() {
    float mn = funmap(g_dmin_u);
    float mx = funmap(g_dmax_u);
    float middle = (mx + mn) * 0.5f;
    float amp = mx - middle + 1e-5f;
    g_middle = middle;
    g_sc = 1.0f / (amp * 0.05f);   // 1/(amplitude * epsilon)
}

// ---------------- P' = exp(sc*(middle - d)) in place ----------------
__global__ void k_transform() {
    size_t i = (size_t)blockIdx.x * blockDim.x + threadIdx.x;
    float mid = g_middle, sc = g_sc;
    float4* P4 = (float4*)g_P;
    float4 v = P4[i];
    v.x = fexp((mid - v.x) * sc);
    v.y = fexp((mid - v.y) * sc);
    v.z = fexp((mid - v.z) * sc);
    v.w = fexp((mid - v.w) * sc);
    P4[i] = v;
}

// ---------------- persistent Sinkhorn: 100 iterations, 1 grid barrier each ----------------
__global__ void __launch_bounds__(512, 1) k_sink() {
    __shared__ float sC[NCOL];
    __shared__ float sacc[NCOL];
    int tid = threadIdx.x, lane = tid & 31, w = tid >> 5;
    int r0 = blockIdx.x * 256;
    unsigned phase = 0;

    for (int j = tid; j < NCOL; j += 512) sC[j] = 1.0f;   // C^(0) = 1
    __syncthreads();

    for (int t = 0; t < ITERS; ++t) {
        for (int j = tid; j < NCOL; j += 512) sacc[j] = 0.0f;
        __syncthreads();

        float4 racc[8];
#pragma unroll
        for (int q = 0; q < 8; ++q) racc[q] = make_float4(0.f, 0.f, 0.f, 0.f);

        for (int rr = 0; rr < 16; ++rr) {
            int row = r0 + w * 16 + rr;
            const float4* pr = (const float4*)(g_P + (size_t)row * NCOL);
            float4 p[8];
            float dot = 0.0f;
#pragma unroll
            for (int q = 0; q < 8; ++q) {
                p[q] = pr[lane + 32 * q];
                float4 c = ((const float4*)sC)[lane + 32 * q];
                dot += p[q].x * c.x + p[q].y * c.y + p[q].z * c.z + p[q].w * c.w;
            }
#pragma unroll
            for (int o = 16; o; o >>= 1) dot += __shfl_xor_sync(0xffffffffu, dot, o);
            float R = 1.0f / (32768.0f * dot);
#pragma unroll
            for (int q = 0; q < 8; ++q) {
                racc[q].x += R * p[q].x; racc[q].y += R * p[q].y;
                racc[q].z += R * p[q].z; racc[q].w += R * p[q].w;
            }
            if (t == ITERS - 1 && lane == 0) g_R[row] = R;
        }

        // warp partials -> block partials (smem atomics, 16x reduced traffic)
#pragma unroll
        for (int q = 0; q < 8; ++q) {
            int jb = (lane + 32 * q) * 4;
            atomicAdd(&sacc[jb + 0], racc[q].x);
            atomicAdd(&sacc[jb + 1], racc[q].y);
            atomicAdd(&sacc[jb + 2], racc[q].z);
            atomicAdd(&sacc[jb + 3], racc[q].w);
        }
        __syncthreads();
        for (int j = tid; j < NCOL; j += 512) atomicAdd(&g_colsum[t][j], sacc[j]);

        // ---- grid barrier ----
        __syncthreads();
        if (tid == 0) {
            __threadfence();
            unsigned arrived = atomicAdd(&g_barrier, 1u) + 1u;
            phase += SINK_BLOCKS;
            if (arrived < phase) {
                while (*(volatile unsigned*)&g_barrier < phase) __nanosleep(64);
            }
        }
        __syncthreads();

        // new C from this iteration's column sums (L2-only loads: skip L1)
        for (int j = tid; j < NCOL; j += 512)
            sC[j] = 1.0f / (1024.0f * __ldcg(&g_colsum[t][j]));
        __syncthreads();
    }
}

// ---------------- final pass: argmax(P'*C), argmax(P') (== argmin d), finiteness ----------------
__global__ void __launch_bounds__(512) k_final() {
    __shared__ float sC[NCOL];
    int tid = threadIdx.x, lane = tid & 31, w = tid >> 5;
    for (int j = tid; j < NCOL; j += 512)
        sC[j] = 1.0f / (1024.0f * g_colsum[ITERS - 1][j]);
    __syncthreads();

    int row = blockIdx.x * 16 + w;
    const float4* pr = (const float4*)(g_P + (size_t)row * NCOL);
    float rb = g_R[row] * 32768.0f;

    float bq = -FLT_MAX; int biq = 0;
    float bp = -FLT_MAX; int bip = 0;
    bool bad = false;
#pragma unroll
    for (int q = 0; q < 8; ++q) {
        float4 p = pr[lane + 32 * q];
        float4 c = ((const float4*)sC)[lane + 32 * q];
        float pv[4] = {p.x, p.y, p.z, p.w};
        float cv[4] = {c.x, c.y, c.z, c.w};
        int jb = (lane + 32 * q) * 4;
#pragma unroll
        for (int e = 0; e < 4; ++e) {
            float qv = pv[e] * cv[e];
            float full = qv * rb;
            if (!(fabsf(full) <= FLT_MAX)) bad = true;   // NaN/Inf
            if (qv > bq) { bq = qv; biq = jb + e; }      // per-lane j ascending: keeps first
            if (pv[e] > bp) { bp = pv[e]; bip = jb + e; }
        }
    }
#pragma unroll
    for (int o = 16; o; o >>= 1) {
        float ov = __shfl_xor_sync(0xffffffffu, bq, o);
        int   oi = __shfl_xor_sync(0xffffffffu, biq, o);
        if (ov > bq || (ov == bq && oi < biq)) { bq = ov; biq = oi; }
        ov = __shfl_xor_sync(0xffffffffu, bp, o);
        oi = __shfl_xor_sync(0xffffffffu, bip, o);
        if (ov > bp || (ov == bp && oi < bip)) { bp = ov; bip = oi; }
    }
    bool anybad = __any_sync(0xffffffffu, bad);
    if (lane == 0) {
        g_idxQ[row] = biq;
        g_idxD[row] = bip;
        if (anybad) atomicOr(&g_bad, 1);
    }
}

// ---------------- output: x_q_st rows, indices, per-block loss partials ----------------
__global__ void k_output(const float* __restrict__ x, const float* __restrict__ W,
                         float* __restrict__ out) {
    __shared__ float spart[8];
    int tid = threadIdx.x, lane = tid & 31, w = tid >> 5;
    int row = blockIdx.x * 8 + w;
    int idx = g_bad ? g_idxD[row] : g_idxQ[row];

    float2 wv = ((const float2*)(W + (size_t)idx * DIM))[lane];
    float2 xv = ((const float2*)(x + (size_t)row * DIM))[lane];
    float dx = wv.x - xv.x, dy = wv.y - xv.y;
    // straight-through forward value: x + (x_q - x), matching reference op order
    float2 st = make_float2(xv.x + dx, xv.y + dy);
    ((float2*)(out + (size_t)row * DIM))[lane] = st;

    float s = dx * dx + dy * dy;
#pragma unroll
    for (int o = 16; o; o >>= 1) s += __shfl_xor_sync(0xffffffffu, s, o);
    if (lane == 0) {
        spart[w] = s;
        out[IDX_OFF + row] = (float)idx;
    }
    __syncthreads();
    if (tid == 0) {
        float t = 0.f;
#pragma unroll
        for (int i = 0; i < 8; ++i) t += spart[i];
        g_losspart[blockIdx.x] = t;
    }
}

__global__ void k_loss(float* __restrict__ out) {
    __shared__ float sp[512];
    int tid = threadIdx.x;
    float s = 0.f;
    for (int i = tid; i < 4096; i += 512) s += g_losspart[i];
    sp[tid] = s;
    __syncthreads();
    for (int o = 256; o; o >>= 1) {
        if (tid < o) sp[tid] += sp[tid + o];
        __syncthreads();
    }
    if (tid == 0) {
        float m = sp[0] / (float)XQ_ELEMS;     // codebook_loss == commitment_loss numerically
        out[LOSS_OFF] = m + 0.25f * m;
    }
}

extern "C" void kernel_launch(void* const* d_in, const int* in_sizes, int n_in,
                              void* d_out, int out_size) {
    const float* x = (const float*)d_in[0];
    const float* W = (const float*)d_in[1];
    float* out = (float*)d_out;

    k_init<<<400, 256>>>();
    k_norms<<<4224, 256>>>(x, W);
    k_gemm<<<dim3(512, 16), 256>>>(x, W);
    k_consts<<<1, 1>>>();
    k_transform<<<32768, 256>>>();
    k_sink<<<SINK_BLOCKS, 512>>>();
    k_final<<<2048, 512>>>();
    k_output<<<4096, 256>>>(x, W, out);
    k_loss<<<1, 512>>>(out);
}

// round 4
// speedup vs baseline: 1.1829x; 1.1829x over previous
#include <cuda_runtime.h>
#include <cstdint>
#include <cfloat>

#define NROW 32768
#define NCOL 1024
#define DIM 64
#define ITERS 100
#define SINK_BLOCKS 128
#define XQ_ELEMS (NROW * DIM)          // 2097152
#define LOSS_OFF XQ_ELEMS
#define IDX_OFF (XQ_ELEMS + 1)

// dynamic smem layout for k_sink: sC[1024] | sacc[16*1024] | sR[16*16]
#define SINK_SMEM_FLOATS (NCOL + 16 * NCOL + 256)
#define SINK_SMEM_BYTES (SINK_SMEM_FLOATS * 4)

// ---------------- device scratch (static: no runtime allocation) ----------------
__device__ float    g_P[(size_t)NROW * NCOL];     // d, then P' = exp(sc*(middle-d)); 134MB
__device__ float    g_xx[NROW];
__device__ float    g_ww[NCOL];
__device__ float    g_colsum[ITERS][NCOL];        // per-iteration column sums
__device__ int      g_idxQ[NROW];
__device__ int      g_idxD[NROW];
__device__ int      g_bad;
__device__ float    g_losspart[4096];
__device__ unsigned g_dmin_u, g_dmax_u;
__device__ float    g_middle, g_sc;
__device__ unsigned g_barrier;

// monotone float<->unsigned map for atomicMin/Max ordering
__device__ __forceinline__ unsigned fmapu(float f) {
    unsigned u = __float_as_uint(f);
    return (u & 0x80000000u) ? ~u : (u | 0x80000000u);
}
__device__ __forceinline__ float funmap(unsigned m) {
    unsigned v = (m & 0x80000000u) ? (m & 0x7fffffffu) : ~m;
    return __uint_as_float(v);
}

// FFMA-only exp (no MUFU). Valid for |x| <= ~25. Max rel err ~1.2e-7.
// (Bit-identical to the R2 passing kernel: argmax gaps validated against it.)
__device__ __forceinline__ float fexp(float x) {
    float t = x * 1.4426950408889634f;   // x * log2(e)
    float r = rintf(t);
    float g = (t - r) * 0.6931471805599453f;   // in [-0.3466, 0.3466]
    float p = 1.0f + g * (1.0f + g * (0.5f + g * (0.16666666667f +
              g * (0.041666666667f + g * (0.0083333333333f + g * 0.0013888888889f)))));
    int ir = (int)r;
    float s = __int_as_float((ir + 127) << 23);
    return p * s;
}

// ---------------- 32-byte evict_last accessors (ptxas requires .v4.b64 with policy) ----
struct F8 { float f[8]; };

__device__ __forceinline__ F8 ldg_evl8(const float* p) {   // keep in L2
    unsigned long long a, b, c, d;
    asm volatile("ld.global.nc.L2::evict_last.v4.b64 {%0,%1,%2,%3}, [%4];"
                 : "=l"(a), "=l"(b), "=l"(c), "=l"(d) : "l"(p));
    F8 r;
    r.f[0] = __uint_as_float((unsigned)a); r.f[1] = __uint_as_float((unsigned)(a >> 32));
    r.f[2] = __uint_as_float((unsigned)b); r.f[3] = __uint_as_float((unsigned)(b >> 32));
    r.f[4] = __uint_as_float((unsigned)c); r.f[5] = __uint_as_float((unsigned)(c >> 32));
    r.f[6] = __uint_as_float((unsigned)d); r.f[7] = __uint_as_float((unsigned)(d >> 32));
    return r;
}
__device__ __forceinline__ F8 ldg_cs8(const float* p) {    // stream through L2
    F8 r;
    float4 a = __ldcs((const float4*)p);
    float4 b = __ldcs((const float4*)p + 1);
    r.f[0] = a.x; r.f[1] = a.y; r.f[2] = a.z; r.f[3] = a.w;
    r.f[4] = b.x; r.f[5] = b.y; r.f[6] = b.z; r.f[7] = b.w;
    return r;
}
__device__ __forceinline__ void stg_evl8(float* p, const F8& v) {
    unsigned long long a = (unsigned long long)__float_as_uint(v.f[0]) |
                           ((unsigned long long)__float_as_uint(v.f[1]) << 32);
    unsigned long long b = (unsigned long long)__float_as_uint(v.f[2]) |
                           ((unsigned long long)__float_as_uint(v.f[3]) << 32);
    unsigned long long c = (unsigned long long)__float_as_uint(v.f[4]) |
                           ((unsigned long long)__float_as_uint(v.f[5]) << 32);
    unsigned long long d = (unsigned long long)__float_as_uint(v.f[6]) |
                           ((unsigned long long)__float_as_uint(v.f[7]) << 32);
    asm volatile("st.global.L2::evict_last.v4.b64 [%0], {%1,%2,%3,%4};"
                 :: "l"(p), "l"(a), "l"(b), "l"(c), "l"(d) : "memory");
}
__device__ __forceinline__ void stg_cs8(float* p, const F8& v) {
    __stcs((float4*)p,     make_float4(v.f[0], v.f[1], v.f[2], v.f[3]));
    __stcs((float4*)p + 1, make_float4(v.f[4], v.f[5], v.f[6], v.f[7]));
}

// ---------------- init: zero per-iteration colsums + scalars ----------------
__global__ void k_init() {
    int i = blockIdx.x * blockDim.x + threadIdx.x;
    if (i < ITERS * NCOL) ((float*)g_colsum)[i] = 0.0f;
    if (i == 0) {
        g_barrier = 0u;
        g_bad = 0;
        g_dmin_u = 0xFFFFFFFFu;
        g_dmax_u = 0u;
    }
}

// ---------------- squared norms: one warp per row ----------------
__global__ void k_norms(const float* __restrict__ x, const float* __restrict__ W) {
    int gw = blockIdx.x * 8 + (threadIdx.x >> 5);
    int lane = threadIdx.x & 31;
    if (gw >= NROW + NCOL) return;
    const float* src = (gw < NROW) ? (x + (size_t)gw * DIM)
                                   : (W + (size_t)(gw - NROW) * DIM);
    float2 v = ((const float2*)src)[lane];
    float s = v.x * v.x + v.y * v.y;
#pragma unroll
    for (int o = 16; o; o >>= 1) s += __shfl_xor_sync(0xffffffffu, s, o);
    if (lane == 0) {
        if (gw < NROW) g_xx[gw] = s;
        else           g_ww[gw - NROW] = s;
    }
}

// ---------------- d = xx + ww - 2 x@W^T (fp32 FFMA, 64x64 tiles); global min/max of d ----------------
__global__ void __launch_bounds__(256) k_gemm(const float* __restrict__ x,
                                              const float* __restrict__ W) {
    __shared__ float xsT[64][68];
    __shared__ float wsT[64][68];
    int tid = threadIdx.x;
    int r0 = blockIdx.x * 64;
    int c0 = blockIdx.y * 64;

    for (int n = tid; n < 1024; n += 256) {
        int r = n >> 4, d4 = (n & 15) << 2;
        float4 v = *(const float4*)(x + (size_t)(r0 + r) * DIM + d4);
        xsT[d4 + 0][r] = v.x; xsT[d4 + 1][r] = v.y;
        xsT[d4 + 2][r] = v.z; xsT[d4 + 3][r] = v.w;
        float4 u = *(const float4*)(W + (size_t)(c0 + r) * DIM + d4);
        wsT[d4 + 0][r] = u.x; wsT[d4 + 1][r] = u.y;
        wsT[d4 + 2][r] = u.z; wsT[d4 + 3][r] = u.w;
    }
    __syncthreads();

    int tx = tid & 15, ty = tid >> 4;
    float acc[4][4];
#pragma unroll
    for (int i = 0; i < 4; ++i)
#pragma unroll
        for (int j = 0; j < 4; ++j) acc[i][j] = 0.0f;

#pragma unroll 8
    for (int d = 0; d < 64; ++d) {
        float4 a = *(const float4*)&xsT[d][ty * 4];
        float4 b = *(const float4*)&wsT[d][tx * 4];
        float av[4] = {a.x, a.y, a.z, a.w};
        float bv[4] = {b.x, b.y, b.z, b.w};
#pragma unroll
        for (int i = 0; i < 4; ++i)
#pragma unroll
            for (int j = 0; j < 4; ++j) acc[i][j] += av[i] * bv[j];
    }

    float mn = FLT_MAX, mx = -FLT_MAX;
#pragma unroll
    for (int i = 0; i < 4; ++i) {
        int row = r0 + ty * 4 + i;
        float xxv = g_xx[row];
        float dv[4];
#pragma unroll
        for (int j = 0; j < 4; ++j) {
            dv[j] = (xxv + g_ww[c0 + tx * 4 + j]) - 2.0f * acc[i][j];
            mn = fminf(mn, dv[j]);
            mx = fmaxf(mx, dv[j]);
        }
        *(float4*)(g_P + (size_t)row * NCOL + c0 + tx * 4) =
            make_float4(dv[0], dv[1], dv[2], dv[3]);
    }

    __shared__ float smn[256], smx[256];
    smn[tid] = mn; smx[tid] = mx;
    __syncthreads();
    for (int s = 128; s; s >>= 1) {
        if (tid < s) {
            smn[tid] = fminf(smn[tid], smn[tid + s]);
            smx[tid] = fmaxf(smx[tid], smx[tid + s]);
        }
        __syncthreads();
    }
    if (tid == 0) {
        atomicMin(&g_dmin_u, fmapu(smn[0]));
        atomicMax(&g_dmax_u, fmapu(smx[0]));
    }
}

// ---------------- scalar constants ----------------
__global__ void k_consts() {
    float mn = funmap(g_dmin_u);
    float mx = funmap(g_dmax_u);
    float middle = (mx + mn) * 0.5f;
    float amp = mx - middle + 1e-5f;
    g_middle = middle;
    g_sc = 1.0f / (amp * 0.05f);   // 1/(amplitude * epsilon)
}

// ---------------- P' = exp(sc*(middle - d)) in place, eviction-hinted ----------------
// pinned rows: (row & 15) < 11  ->  88MB kept resident in L2 for the sinkhorn loop
__global__ void k_transform() {
    size_t i = (size_t)blockIdx.x * blockDim.x + threadIdx.x;   // 8-float chunk index
    float mid = g_middle, sc = g_sc;
    float* p = g_P + i * 8;
    F8 v = ldg_cs8(p);                          // d is dead after this read
#pragma unroll
    for (int e = 0; e < 8; ++e) v.f[e] = fexp((mid - v.f[e]) * sc);
    bool pinned = (((i >> 7) & 15) < 11);       // row = i*8/1024 = i/128
    if (pinned) stg_evl8(p, v);
    else        stg_cs8(p, v);
}

// ---------------- persistent Sinkhorn: 100 iterations + fused final argmax ----------------
__global__ void __launch_bounds__(512, 1) k_sink() {
    extern __shared__ float sm[];
    float* sC   = sm;                     // [1024]  current column factors
    float* sacc = sm + NCOL;              // [16][1024] per-warp column partials
    float* sR   = sm + NCOL + 16 * NCOL;  // [16][16] last-iter row factors
    int tid = threadIdx.x, lane = tid & 31, w = tid >> 5;
    int r0 = blockIdx.x * 256;
    unsigned phase = 0;

    for (int j = tid; j < NCOL; j += 512) sC[j] = 1.0f;   // C^(0) = 1
    __syncthreads();

    for (int t = 0; t < ITERS; ++t) {
        F8 racc[4];
#pragma unroll
        for (int q = 0; q < 4; ++q)
#pragma unroll
            for (int e = 0; e < 8; ++e) racc[q].f[e] = 0.0f;

#pragma unroll
        for (int rr = 0; rr < 16; ++rr) {
            int row = r0 + w * 16 + rr;            // (row & 15) == rr
            const float* pr = g_P + (size_t)row * NCOL;
            F8 p[4];
            if (rr < 11) {
#pragma unroll
                for (int q = 0; q < 4; ++q) p[q] = ldg_evl8(pr + lane * 8 + 256 * q);
            } else {
#pragma unroll
                for (int q = 0; q < 4; ++q) p[q] = ldg_cs8(pr + lane * 8 + 256 * q);
            }
            float dot = 0.0f;
#pragma unroll
            for (int q = 0; q < 4; ++q) {
                const float* cv = sC + lane * 8 + 256 * q;
                float4 c0 = *(const float4*)cv;
                float4 c1 = *(const float4*)(cv + 4);
                dot += p[q].f[0] * c0.x + p[q].f[1] * c0.y + p[q].f[2] * c0.z + p[q].f[3] * c0.w
                     + p[q].f[4] * c1.x + p[q].f[5] * c1.y + p[q].f[6] * c1.z + p[q].f[7] * c1.w;
            }
#pragma unroll
            for (int o = 16; o; o >>= 1) dot += __shfl_xor_sync(0xffffffffu, dot, o);
            float R = 1.0f / (32768.0f * dot);
#pragma unroll
            for (int q = 0; q < 4; ++q)
#pragma unroll
                for (int e = 0; e < 8; ++e) racc[q].f[e] += R * p[q].f[e];
            if (lane == 0) sR[w * 16 + rr] = R;    // last write (t=99) survives the loop
        }

        // deterministic staged reduction: warp partials -> smem -> global atomics
#pragma unroll
        for (int q = 0; q < 4; ++q) {
            float* dst = sacc + w * NCOL + lane * 8 + 256 * q;
            *(float4*)dst       = make_float4(racc[q].f[0], racc[q].f[1], racc[q].f[2], racc[q].f[3]);
            *(float4*)(dst + 4) = make_float4(racc[q].f[4], racc[q].f[5], racc[q].f[6], racc[q].f[7]);
        }
        __syncthreads();
        for (int j = tid; j < NCOL; j += 512) {
            float s = 0.0f;
#pragma unroll
            for (int ww = 0; ww < 16; ++ww) s += sacc[ww * NCOL + j];
            atomicAdd(&g_colsum[t][j], s);
        }

        // ---- grid barrier (all threads fence so their REDs are globally visible) ----
        __threadfence();
        __syncthreads();
        if (tid == 0) {
            unsigned arrived = atomicAdd(&g_barrier, 1u) + 1u;
            phase += SINK_BLOCKS;
            if (arrived < phase) {
                while (*(volatile unsigned*)&g_barrier < phase) __nanosleep(64);
            }
        }
        __syncthreads();

        // new C from this iteration's column sums
        for (int j = tid; j < NCOL; j += 512)
            sC[j] = 1.0f / (1024.0f * __ldcg(&g_colsum[t][j]));
        __syncthreads();
    }

    // ---- fused final pass: argmax(P'*C_final), argmax(P') (== argmin d), finiteness ----
    // sC holds C_final; pinned rows are warm in L2 from iteration 99.
#pragma unroll
    for (int rr = 0; rr < 16; ++rr) {
        int row = r0 + w * 16 + rr;
        const float* pr = g_P + (size_t)row * NCOL;
        float rb = sR[w * 16 + rr] * 32768.0f;

        float bq = -FLT_MAX; int biq = 0;
        float bp = -FLT_MAX; int bip = 0;
        bool bad = false;
#pragma unroll
        for (int q = 0; q < 4; ++q) {
            F8 p = (rr < 11) ? ldg_evl8(pr + lane * 8 + 256 * q)
                             : ldg_cs8(pr + lane * 8 + 256 * q);
            const float* cv = sC + lane * 8 + 256 * q;
            int jb = lane * 8 + 256 * q;
#pragma unroll
            for (int e = 0; e < 8; ++e) {
                float qv = p.f[e] * cv[e];
                float full = qv * rb;
                if (!(fabsf(full) <= FLT_MAX)) bad = true;     // NaN/Inf
                if (qv > bq) { bq = qv; biq = jb + e; }        // per-lane j ascending: keeps first
                if (p.f[e] > bp) { bp = p.f[e]; bip = jb + e; }
            }
        }
#pragma unroll
        for (int o = 16; o; o >>= 1) {
            float ov = __shfl_xor_sync(0xffffffffu, bq, o);
            int   oi = __shfl_xor_sync(0xffffffffu, biq, o);
            if (ov > bq || (ov == bq && oi < biq)) { bq = ov; biq = oi; }
            ov = __shfl_xor_sync(0xffffffffu, bp, o);
            oi = __shfl_xor_sync(0xffffffffu, bip, o);
            if (ov > bp || (ov == bp && oi < bip)) { bp = ov; bip = oi; }
        }
        bool anybad = __any_sync(0xffffffffu, bad);
        if (lane == 0) {
            g_idxQ[row] = biq;
            g_idxD[row] = bip;
            if (anybad) atomicOr(&g_bad, 1);
        }
    }
}

// ---------------- output: x_q_st rows, indices, per-block loss partials ----------------
__global__ void k_output(const float* __restrict__ x, const float* __restrict__ W,
                         float* __restrict__ out) {
    __shared__ float spart[8];
    int tid = threadIdx.x, lane = tid & 31, w = tid >> 5;
    int row = blockIdx.x * 8 + w;
    int idx = g_bad ? g_idxD[row] : g_idxQ[row];

    float2 wv = ((const float2*)(W + (size_t)idx * DIM))[lane];
    float2 xv = ((const float2*)(x + (size_t)row * DIM))[lane];
    float dx = wv.x - xv.x, dy = wv.y - xv.y;
    float2 st = make_float2(xv.x + dx, xv.y + dy);   // x + (x_q - x), reference op order
    ((float2*)(out + (size_t)row * DIM))[lane] = st;

    float s = dx * dx + dy * dy;
#pragma unroll
    for (int o = 16; o; o >>= 1) s += __shfl_xor_sync(0xffffffffu, s, o);
    if (lane == 0) {
        spart[w] = s;
        out[IDX_OFF + row] = (float)idx;
    }
    __syncthreads();
    if (tid == 0) {
        float t = 0.f;
#pragma unroll
        for (int i = 0; i < 8; ++i) t += spart[i];
        g_losspart[blockIdx.x] = t;
    }
}

__global__ void k_loss(float* __restrict__ out) {
    __shared__ float sp[512];
    int tid = threadIdx.x;
    float s = 0.f;
    for (int i = tid; i < 4096; i += 512) s += g_losspart[i];
    sp[tid] = s;
    __syncthreads();
    for (int o = 256; o; o >>= 1) {
        if (tid < o) sp[tid] += sp[tid + o];
        __syncthreads();
    }
    if (tid == 0) {
        float m = sp[0] / (float)XQ_ELEMS;
        out[LOSS_OFF] = m + 0.25f * m;
    }
}

extern "C" void kernel_launch(void* const* d_in, const int* in_sizes, int n_in,
                              void* d_out, int out_size) {
    const float* x = (const float*)d_in[0];
    const float* W = (const float*)d_in[1];
    float* out = (float*)d_out;

    static bool attr_set = false;
    if (!attr_set) {
        cudaFuncSetAttribute(k_sink, cudaFuncAttributeMaxDynamicSharedMemorySize,
                             SINK_SMEM_BYTES);
        attr_set = true;
    }

    k_init<<<400, 256>>>();
    k_norms<<<4224, 256>>>(x, W);
    k_gemm<<<dim3(512, 16), 256>>>(x, W);
    k_consts<<<1, 1>>>();
    k_transform<<<16384, 256>>>();
    k_sink<<<SINK_BLOCKS, 512, SINK_SMEM_BYTES>>>();
    k_output<<<4096, 256>>>(x, W, out);
    k_loss<<<1, 512>>>(out);
}